// round 9
// baseline (speedup 1.0000x reference)
#include <cuda_runtime.h>
#include <cuda_bf16.h>
#include <cstdint>

// Problem constants (shapes fixed by the dataset)
#define N_NODES_MAX 100000
#define D 64
#define OUT 64
#define LN_EPS 1e-5f

// Scratch: neighbor_sum accumulator [N, D] — device global (no allocs allowed)
__device__ __align__(16) float g_nsum[N_NODES_MAX * D];

// ---------------------------------------------------------------------------
// Kernel 1: scatter-add. 16 lanes per edge; lane handles float4 chunk `sub`.
// red.global.add.v4.f32: 4 floats per instruction, no return value.
// Dtype detection per-block (proven harmless in R5): if edge_index is int32
// pairs read as int64, high halves are ~uniform node indices ->
// P(first 256 words all look like valid int64) ~ 1e-1280.
// ---------------------------------------------------------------------------
__global__ void __launch_bounds__(256) scatter_kernel(
    const float4* __restrict__ x4,
    const void* __restrict__ ei_raw,
    int n_edges, int n_nodes) {

    const long long* ei64 = reinterpret_cast<const long long*>(ei_raw);
    const int*       ei32 = reinterpret_cast<const int*>(ei_raw);

    // per-block dtype detection (reads first 256 int64 words, L2-cached)
    int bad = 0;
    {
        int nw = n_edges / 2;           // int64 words guaranteed to exist
        if (nw > 256) nw = 256;
        if ((int)threadIdx.x < nw) {
            long long v = ei64[threadIdx.x];
            bad = (v < 0 || v >= (long long)n_nodes) ? 1 : 0;
        }
    }
    const int is64 = !__syncthreads_or(bad);

    const int t   = blockIdx.x * blockDim.x + threadIdx.x;
    const int sub = t & 15;
    int e = t >> 4;
    const int estride = (gridDim.x * blockDim.x) >> 4;
    float4* __restrict__ nsum4 = reinterpret_cast<float4*>(g_nsum);

    if (is64) {
        for (; e < n_edges; e += estride) {
            long long row = ei64[e];
            long long col = ei64[n_edges + e];
            float4 v = x4[row * 16 + sub];
            float4* dst = &nsum4[col * 16 + sub];
            asm volatile("red.global.add.v4.f32 [%0], {%1, %2, %3, %4};"
                         :: "l"(dst), "f"(v.x), "f"(v.y), "f"(v.z), "f"(v.w)
                         : "memory");
        }
    } else {
        for (; e < n_edges; e += estride) {
            long long row = ei32[e];
            long long col = ei32[n_edges + e];
            float4 v = x4[row * 16 + sub];
            float4* dst = &nsum4[col * 16 + sub];
            asm volatile("red.global.add.v4.f32 [%0], {%1, %2, %3, %4};"
                         :: "l"(dst), "f"(v.x), "f"(v.y), "f"(v.z), "f"(v.w)
                         : "memory");
        }
    }
}

// ---------------------------------------------------------------------------
// Kernel 2: fused concat + Linear(128->64) + bias + LayerNorm.
// R8's node-packed 8x4 tile, but W is read through L1 (__ldg) instead of
// shared -> smem is A-only (64KB) -> 3 blocks/SM instead of 2.
//   block = 128 nodes x 64 outs, 256 threads, thread tile = 8 nodes x 4 outs.
// Inner loop per k per thread:
//   2x LDS.128 (a-pairs, node-packed, no dup movs)
//   1x LDG.128 (W row, L1-resident 32KB)
//   4x mov.b64 (W dups) + 16x fma.rn.f32x2
// ---------------------------------------------------------------------------
#define TILE_N 128
#define NTHR   256

__global__ void __launch_bounds__(NTHR, 3) gemm_ln_kernel(
    const float4* __restrict__ x4,
    const float4* __restrict__ W4,
    const float*  __restrict__ b,
    const float*  __restrict__ gamma,
    const float*  __restrict__ beta,
    float4* __restrict__ out4,
    int n_nodes) {

    extern __shared__ char smem_raw[];
    float* Ash = reinterpret_cast<float*>(smem_raw);   // [128][128] = 64KB

    const int tid = threadIdx.x;
    const int tx  = tid & 15;   // outs 4tx..4tx+3
    const int ty  = tid >> 4;   // nodes 8ty..8ty+7
    const int node_base = blockIdx.x * TILE_N;

    // stage A transposed: Ash[k][n] = concat(x, nsum)[node_base+n][k]
    {
        const float4* nsum4 = reinterpret_cast<const float4*>(g_nsum);
        #pragma unroll
        for (int it = 0; it < 16; it++) {
            int idx = it * NTHR + tid;
            int n = idx & 127;         // lanes consecutive in n -> STS conflict-free
            int r = idx >> 7;          // k-quad 0..31
            int gn = node_base + n;
            float4 v = make_float4(0.f, 0.f, 0.f, 0.f);
            if (gn < n_nodes)
                v = (r < 16) ? x4[(long long)gn * 16 + r]
                             : nsum4[(long long)gn * 16 + (r - 16)];
            int k0 = 4 * r;
            Ash[(k0 + 0) * 128 + n] = v.x;
            Ash[(k0 + 1) * 128 + n] = v.y;
            Ash[(k0 + 2) * 128 + n] = v.z;
            Ash[(k0 + 3) * 128 + n] = v.w;
        }
    }
    __syncthreads();

    // acc[i][j]: node-pair i (nodes 2i,2i+1 of this thread's 8) x out j
    unsigned long long acc[4][4];
    #pragma unroll
    for (int i = 0; i < 4; i++)
        #pragma unroll
        for (int j = 0; j < 4; j++) acc[i][j] = 0ull;

    const unsigned long long* ab =
        reinterpret_cast<const unsigned long long*>(Ash + 8 * ty);
    const float4* wg = W4 + tx;    // W row k: 16 float4s; this thread uses [k*16+tx]

    #pragma unroll 8
    for (int k = 0; k < 128; k++) {
        // 4 node-pairs, naturally packed (adjacent floats in Ash row)
        ulonglong2 a01 = *reinterpret_cast<const ulonglong2*>(ab + k * 64);
        ulonglong2 a23 = *reinterpret_cast<const ulonglong2*>(ab + k * 64 + 2);
        float4 wv = __ldg(wg + k * 16);
        unsigned long long wd[4];
        asm("mov.b64 %0, {%1, %1};" : "=l"(wd[0]) : "f"(wv.x));
        asm("mov.b64 %0, {%1, %1};" : "=l"(wd[1]) : "f"(wv.y));
        asm("mov.b64 %0, {%1, %1};" : "=l"(wd[2]) : "f"(wv.z));
        asm("mov.b64 %0, {%1, %1};" : "=l"(wd[3]) : "f"(wv.w));
        unsigned long long ap[4] = {a01.x, a01.y, a23.x, a23.y};
        #pragma unroll
        for (int i = 0; i < 4; i++) {
            asm("fma.rn.f32x2 %0, %1, %2, %0;" : "+l"(acc[i][0]) : "l"(ap[i]), "l"(wd[0]));
            asm("fma.rn.f32x2 %0, %1, %2, %0;" : "+l"(acc[i][1]) : "l"(ap[i]), "l"(wd[1]));
            asm("fma.rn.f32x2 %0, %1, %2, %0;" : "+l"(acc[i][2]) : "l"(ap[i]), "l"(wd[2]));
            asm("fma.rn.f32x2 %0, %1, %2, %0;" : "+l"(acc[i][3]) : "l"(ap[i]), "l"(wd[3]));
        }
    }

    // epilogue: unpack (node 2i+di, out j), bias + LayerNorm + store
    const float4 bj = reinterpret_cast<const float4*>(b)[tx];
    const float4 gj = reinterpret_cast<const float4*>(gamma)[tx];
    const float4 ej = reinterpret_cast<const float4*>(beta)[tx];
    const float bja[4] = {bj.x, bj.y, bj.z, bj.w};

    float val[8][4];   // [node 0..7][out 0..3]
    #pragma unroll
    for (int i = 0; i < 4; i++)
        #pragma unroll
        for (int j = 0; j < 4; j++) {
            val[2 * i][j]     = __uint_as_float((unsigned)(acc[i][j] & 0xffffffffull)) + bja[j];
            val[2 * i + 1][j] = __uint_as_float((unsigned)(acc[i][j] >> 32))           + bja[j];
        }

    float s[8], ss[8];
    #pragma unroll
    for (int i = 0; i < 8; i++) {
        s[i]  = val[i][0] + val[i][1] + val[i][2] + val[i][3];
        ss[i] = val[i][0] * val[i][0] + val[i][1] * val[i][1]
              + val[i][2] * val[i][2] + val[i][3] * val[i][3];
    }
    // reduce across the 16 tx lanes (xor masks stay inside each 16-lane half)
    #pragma unroll
    for (int m = 1; m < 16; m <<= 1) {
        #pragma unroll
        for (int i = 0; i < 8; i++) {
            s[i]  += __shfl_xor_sync(0xFFFFFFFFu, s[i],  m);
            ss[i] += __shfl_xor_sync(0xFFFFFFFFu, ss[i], m);
        }
    }

    const float inv64 = 1.0f / 64.0f;
    #pragma unroll
    for (int i = 0; i < 8; i++) {
        float mu  = s[i] * inv64;
        float var = ss[i] * inv64 - mu * mu;
        float rs  = rsqrtf(var + LN_EPS);
        int gn = node_base + 8 * ty + i;
        if (gn < n_nodes) {
            float4 o;
            o.x = (val[i][0] - mu) * rs * gj.x + ej.x;
            o.y = (val[i][1] - mu) * rs * gj.y + ej.y;
            o.z = (val[i][2] - mu) * rs * gj.z + ej.z;
            o.w = (val[i][3] - mu) * rs * gj.w + ej.w;
            out4[(long long)gn * 16 + tx] = o;
        }
    }
}

// ---------------------------------------------------------------------------
// launch
// ---------------------------------------------------------------------------
extern "C" void kernel_launch(void* const* d_in, const int* in_sizes, int n_in,
                              void* d_out, int out_size) {
    const float* x     = (const float*)d_in[0];
    const void*  ei    = d_in[1];
    const float* W     = (const float*)d_in[2];
    const float* b     = (const float*)d_in[3];
    const float* gamma = (const float*)d_in[4];
    const float* beta  = (const float*)d_in[5];
    float* out = (float*)d_out;

    const int n_nodes = in_sizes[0] / D;      // 100000
    const int n_edges = in_sizes[1] / 2;      // 1000000

    // dynamic smem: A only (64KB) -> 3 blocks/SM
    cudaFuncSetAttribute(gemm_ln_kernel,
                         cudaFuncAttributeMaxDynamicSharedMemorySize, 65536);

    // 0: zero accumulator via memset node (graph-capturable, no kernel)
    static void* nsum_ptr = nullptr;
    if (!nsum_ptr) cudaGetSymbolAddress(&nsum_ptr, g_nsum);
    cudaMemsetAsync(nsum_ptr, 0, (size_t)n_nodes * D * sizeof(float), 0);

    // 1: scatter (16 lanes/edge, vectorized red.v4, per-block dtype detect)
    scatter_kernel<<<2368, 256>>>((const float4*)x, ei, n_edges, n_nodes);

    // 2: fused GEMM + LayerNorm (8x4 node-packed tile, W via L1, A-only smem)
    int gemm_blocks = (n_nodes + TILE_N - 1) / TILE_N;
    gemm_ln_kernel<<<gemm_blocks, NTHR, 65536>>>(
        (const float4*)x, (const float4*)W, b, gamma, beta,
        (float4*)out, n_nodes);
}